// round 13
// baseline (speedup 1.0000x reference)
#include <cuda_runtime.h>
#include <cuda_fp16.h>
#include <math.h>
#include <stdint.h>

#define Bv 128
#define Tv 256
#define Hv 1024
#define GRID 256
#define NTHR 256

// ---------------- scratch -----------------------------------------------------
__device__ __half g_x16[(size_t)Bv * Tv * Hv];
__device__ __half g_Wt[4][(size_t)Hv * Hv];           // [n][k] fp16: 0:Wh0 1:Wi1 2:Wh1 3:Wi0
__device__ __half g_h0[2][Bv * Hv], g_h1[2][Bv * Hv]; // fp16 ping-pong states
__device__ float g_bsum[2 * Hv];
__device__ float g_Q[64][4][4096];                    // per-quad partial tiles (64x64)
__device__ unsigned g_qcnt[64];                       // quad completion counters
__device__ unsigned g_arrive, g_gen;

// ---------------- smem layout (dynamic, 80 KB -> 2 CTAs/SM) ----------------------
#define OFF_WRES  0
#define OFF_A(b)  (65536 + (b) * 8192)
#define OFF_CMB   65536
#define SMEM_SZ   81920

// ---------------- PTX helpers ---------------------------------------------------
__device__ __forceinline__ uint32_t smem_u32(const void* p) {
    uint32_t a;
    asm("{ .reg .u64 t; cvta.to.shared.u64 t, %1; cvt.u32.u64 %0, t; }" : "=r"(a) : "l"(p));
    return a;
}
__device__ __forceinline__ uint32_t swz(uint32_t o) { return o ^ ((o >> 3) & 0x70); }
__device__ __forceinline__ void cp16(uint32_t s, const void* g) {
    asm volatile("cp.async.cg.shared.global [%0], [%1], 16;" :: "r"(s), "l"(g));
}
__device__ __forceinline__ void ldm4(uint32_t* r, uint32_t addr) {
    asm volatile("ldmatrix.sync.aligned.m8n8.x4.shared.b16 {%0,%1,%2,%3}, [%4];"
        : "=r"(r[0]), "=r"(r[1]), "=r"(r[2]), "=r"(r[3]) : "r"(addr));
}
__device__ __forceinline__ void mma16816(float* c, const uint32_t* a, const uint32_t* b) {
    asm volatile("mma.sync.aligned.m16n8k16.row.col.f32.f16.f16.f32 "
        "{%0,%1,%2,%3}, {%4,%5,%6,%7}, {%8,%9}, {%0,%1,%2,%3};"
        : "+f"(c[0]), "+f"(c[1]), "+f"(c[2]), "+f"(c[3])
        : "r"(a[0]), "r"(a[1]), "r"(a[2]), "r"(a[3]), "r"(b[0]), "r"(b[1]));
}

// ---------------- grid barrier (busy-wait) ----------------------------------------
__device__ __forceinline__ void gbar(unsigned expect) {
    __threadfence();
    __syncthreads();
    if (threadIdx.x == 0) {
        unsigned a = atomicAdd(&g_arrive, 1u);
        if (a == GRID - 1) {
            atomicExch(&g_arrive, 0u);
            __threadfence();
            atomicAdd(&g_gen, 1u);
        } else {
            while (*(volatile unsigned*)&g_gen < expect) {}
        }
        __threadfence();
    }
    __syncthreads();
}

// ---------------- prep kernels -------------------------------------------------------
__global__ void __launch_bounds__(256) k_init(const float* __restrict__ h0in,
                                              const float* __restrict__ bi,
                                              const float* __restrict__ bh)
{
    int idx = blockIdx.x * 256 + threadIdx.x;   // 512 blocks = Bv*Hv
    if (idx == 0) { g_arrive = 0u; g_gen = 0u; }
    if (idx < 64) g_qcnt[idx] = 0u;
    if (idx < 2 * Hv) g_bsum[idx] = bi[idx] + bh[idx];
    int j = idx & (Hv - 1);
    __half v0 = __float2half_rn(h0in[j]);
    __half v1 = __float2half_rn(h0in[Hv + j]);
    g_h0[0][idx] = v0; g_h0[1][idx] = v0;
    g_h1[0][idx] = v1; g_h1[1][idx] = v1;
}

__global__ void __launch_bounds__(256) k_cvtx(const float* __restrict__ x)
{
    size_t i = (size_t)blockIdx.x * 256 + threadIdx.x;
    float4 v = ((const float4*)x)[i];
    __half2 a = __floats2half2_rn(v.x, v.y);
    __half2 b = __floats2half2_rn(v.z, v.w);
    uint2 o;
    o.x = *(uint32_t*)&a;
    o.y = *(uint32_t*)&b;
    ((uint2*)g_x16)[i] = o;
}

__global__ void k_cvtw(const float* __restrict__ Wi, const float* __restrict__ Wh)
{
    __shared__ float t[32][33];
    int m = blockIdx.z;
    const float* W = (m == 0) ? Wh
                   : (m == 1) ? (Wi + (size_t)Hv * Hv)
                   : (m == 2) ? (Wh + (size_t)Hv * Hv) : Wi;
    int k0 = blockIdx.y * 32, n0 = blockIdx.x * 32;
    for (int r = threadIdx.y; r < 32; r += 8)
        t[r][threadIdx.x] = W[(size_t)(k0 + r) * Hv + n0 + threadIdx.x];
    __syncthreads();
    for (int r = threadIdx.y; r < 32; r += 8)
        g_Wt[m][(size_t)(n0 + r) * Hv + k0 + threadIdx.x] = __float2half_rn(t[threadIdx.x][r]);
}

// ---------------- persistent wavefront kernel -----------------------------------------
// 256 CTAs: blockIdx = ctc*4 + rh*2 + ks.
//   ctc: seg = ctc>>4 (0:h0@Wh0 1:h0@Wi1 2:h1@Wh1 3:x@Wi0), ctn = ctc&15.
//   rh: 64-row half.  ks: K-half.
// Quads: {seg0,seg3}x{ks} produce pre-h0; {seg1,seg2}x{ks} produce pre-h1.
// Last finisher of each quad fuses bias+tanh epilogue. ONE grid barrier per wave.
__global__ void __launch_bounds__(NTHR, 2)
k_persist(float* __restrict__ out, int has_hn)
{
    extern __shared__ char smem[];
    __shared__ unsigned s_last;
    const uint32_t sb = smem_u32(smem);
    const int tid  = threadIdx.x;
    const int lane = tid & 31;
    const int wid  = tid >> 5;
    const int ks   = blockIdx.x & 1;
    const int rh   = (blockIdx.x >> 1) & 1;
    const int ctc  = blockIdx.x >> 2;
    const int r0   = rh * 64;
    const int seg  = ctc >> 4;
    const int nloc = (ctc & 15) * 64;
    const int kbase = ks * 8;

    const int L    = (seg == 1 || seg == 2) ? 1 : 0;
    const int qid  = L * 32 + rh * 16 + (ctc & 15);
    const int slot = ((seg >= 2) ? 2 : 0) + ks;

    const int tw = wid & 3, khalf = wid >> 2;
    const int wr = tw & 1, wc = tw >> 1;

    const int mA    = wr * 32 + ((lane >> 3) & 1) * 8 + (lane & 7);
    const uint32_t xorA   = (uint32_t)((mA & 7) * 16);
    const uint32_t abase0 = (uint32_t)(mA * 128);
    const uint32_t abase1 = (uint32_t)((mA + 16) * 128);

    const int nW    = wc * 32 + ((lane >> 4) & 1) * 8 + (lane & 7);
    const uint32_t xorW   = (uint32_t)((nW & 7) * 16);
    const uint32_t wbase0 = (uint32_t)(nW * 128);
    const uint32_t wbase1 = wbase0 + 16 * 128;

    const __half* Wb = g_Wt[seg] + (size_t)nloc * Hv;

    auto load_tile = [&](uint32_t dst, const __half* src, size_t rs) {
#pragma unroll
        for (int r = 0; r < 2; r++) {
            int i = tid + r * 256;
            int row = i >> 3, kg = i & 7;
            cp16(dst + swz(row * 128 + kg * 16), src + (size_t)row * rs + kg * 8);
        }
    };

    // ---- resident W slice for this K-half (once) ----
    for (int c = 0; c < 8; c++)
        load_tile(sb + OFF_WRES + c * 8192, Wb + (kbase + c) * 64, Hv);
    asm volatile("cp.async.commit_group;" ::: "memory");
    asm volatile("cp.async.wait_group 0;" ::: "memory");
    __syncthreads();

    unsigned expect = 0;

    for (int w = 0; w <= Tv; w++) {
        const int p = w & 1;
        // L0 (pre-h0 for t=w): active while w < Tv. L1 (pre-h1 for t=w-1): active w >= 1.
        const bool active = (L == 0) ? (w < Tv) : (w >= 1);

        if (active) {
            const __half* A;
            size_t astr;
            if (seg <= 1)      { A = g_h0[p] + (size_t)r0 * Hv; astr = Hv; }
            else if (seg == 2) { A = g_h1[p] + (size_t)r0 * Hv; astr = Hv; }
            else { A = g_x16 + ((size_t)r0 * Tv + w) * Hv; astr = (size_t)Tv * Hv; }

            auto load_chunk = [&](int b, int c) {
                load_tile(sb + OFF_A(b), A + (kbase + c) * 64, astr);
                asm volatile("cp.async.commit_group;" ::: "memory");
            };

            float acc[8][4];
#pragma unroll
            for (int i = 0; i < 8; i++)
#pragma unroll
                for (int q = 0; q < 4; q++) acc[i][q] = 0.f;

            load_chunk(0, 0);
            load_chunk(1, 1);

#pragma unroll 1
            for (int c = 0; c < 8; c++) {
                const int b = c & 1;
                if (c < 7) asm volatile("cp.async.wait_group 1;" ::: "memory");
                else       asm volatile("cp.async.wait_group 0;" ::: "memory");
                __syncthreads();

                const uint32_t sWr = sb + OFF_WRES + c * 8192;
                uint32_t a0[4], a1[4], wf[8];
#pragma unroll
                for (int kq = 0; kq < 2; kq++) {
                    const int kk = khalf * 2 + kq;
                    uint32_t ka = ((uint32_t)(kk * 32 + ((lane >> 4) & 1) * 16)) ^ xorA;
                    uint32_t kw = ((uint32_t)(kk * 32 + ((lane >> 3) & 1) * 16)) ^ xorW;
                    ldm4(a0, sb + OFF_A(b) + abase0 + ka);
                    ldm4(a1, sb + OFF_A(b) + abase1 + ka);
                    ldm4(wf,     sWr + wbase0 + kw);
                    ldm4(wf + 4, sWr + wbase1 + kw);
#pragma unroll
                    for (int i = 0; i < 2; i++) {
                        const uint32_t* aa = i ? a1 : a0;
#pragma unroll
                        for (int j = 0; j < 4; j++)
                            mma16816(acc[i * 4 + j], aa, &wf[(j >> 1) * 4 + (j & 1) * 2]);
                    }
                }
                __syncthreads();
                if (c + 2 < 8) load_chunk(b, c + 2);
            }

            // ---- combine khalves via smem; khalf0 warps write quad partial ----
            float* cmb = (float*)(smem + OFF_CMB + tw * 4096);
            if (khalf) {
#pragma unroll
                for (int r = 0; r < 32; r++)
                    cmb[r * 32 + lane] = acc[r >> 2][r & 3];
            }
            __syncthreads();
            if (!khalf) {
#pragma unroll
                for (int r = 0; r < 32; r++)
                    acc[r >> 2][r & 3] += cmb[r * 32 + lane];
                float* Cg = g_Q[qid][slot];
                const int g = lane >> 2, tq = lane & 3;
#pragma unroll
                for (int i = 0; i < 2; i++) {
                    float* Cb = Cg + (size_t)(wr * 32 + i * 16 + g) * 64 + wc * 32 + tq * 2;
#pragma unroll
                    for (int j = 0; j < 4; j++) {
                        int t = i * 4 + j;
                        float2 v0, v1;
                        v0.x = acc[t][0]; v0.y = acc[t][1];
                        v1.x = acc[t][2]; v1.y = acc[t][3];
                        *(float2*)(Cb + j * 8) = v0;
                        *(float2*)(Cb + 8 * 64 + j * 8) = v1;
                    }
                }
            }
            __syncthreads();

            // ---- quad counter: last finisher runs the fused epilogue ----
            if (tid == 0) {
                __threadfence();
                unsigned old = atomicAdd(&g_qcnt[qid], 1u);
                s_last = ((old & 3u) == 3u) ? 1u : 0u;
                if (s_last) __threadfence();
            }
            __syncthreads();

            if (s_last) {
                const float* q0 = g_Q[qid][0];
                const float* q1 = g_Q[qid][1];
                const float* q2 = g_Q[qid][2];
                const float* q3 = g_Q[qid][3];
                const int rr = tid >> 2;          // 0..63
                const int cc = (tid & 3) << 4;    // 0,16,32,48
                const int grow = r0 + rr;
                const int gcol = nloc + cc;
                const size_t off = (size_t)rr * 64 + cc;
                const float* bsp = g_bsum + (L ? Hv : 0) + gcol;
                __half* Hs = L ? g_h1[p ^ 1] : g_h0[p ^ 1];

                float4 z[4];
#pragma unroll
                for (int u = 0; u < 4; u++) {
                    float4 a = __ldcg((const float4*)(q0 + off) + u);
                    float4 b = __ldcg((const float4*)(q1 + off) + u);
                    float4 c = __ldcg((const float4*)(q2 + off) + u);
                    float4 d = __ldcg((const float4*)(q3 + off) + u);
                    float4 bs = *((const float4*)bsp + u);
                    z[u].x = tanhf(a.x + b.x + c.x + d.x + bs.x);
                    z[u].y = tanhf(a.y + b.y + c.y + d.y + bs.y);
                    z[u].z = tanhf(a.z + b.z + c.z + d.z + bs.z);
                    z[u].w = tanhf(a.w + b.w + c.w + d.w + bs.w);
                }
                // fp16 state (16 contiguous cols = 2x uint4)
                uint32_t hp[8];
#pragma unroll
                for (int u = 0; u < 4; u++) {
                    __half2 h01 = __floats2half2_rn(z[u].x, z[u].y);
                    __half2 h23 = __floats2half2_rn(z[u].z, z[u].w);
                    hp[u * 2]     = *(uint32_t*)&h01;
                    hp[u * 2 + 1] = *(uint32_t*)&h23;
                }
                *(uint4*)&Hs[(size_t)grow * Hv + gcol]     = make_uint4(hp[0], hp[1], hp[2], hp[3]);
                *(uint4*)&Hs[(size_t)grow * Hv + gcol + 8] = make_uint4(hp[4], hp[5], hp[6], hp[7]);

                if (L == 1) {
                    float* orow = out + ((size_t)grow * Tv + (w - 1)) * Hv + gcol;
#pragma unroll
                    for (int u = 0; u < 4; u++) ((float4*)orow)[u] = z[u];
                    if (w == Tv && has_hn) {
                        float* hn = out + (size_t)Bv * Tv * Hv + (size_t)grow * 2 * Hv + Hv + gcol;
#pragma unroll
                        for (int u = 0; u < 4; u++) ((float4*)hn)[u] = z[u];
                    }
                } else if (w == Tv - 1 && has_hn) {
                    float* hn = out + (size_t)Bv * Tv * Hv + (size_t)grow * 2 * Hv + gcol;
#pragma unroll
                    for (int u = 0; u < 4; u++) ((float4*)hn)[u] = z[u];
                }
            }
        }
        gbar(++expect);
    }
}

// ---------------- launcher -----------------------------------------------------------
extern "C" void kernel_launch(void* const* d_in, const int* in_sizes, int n_in,
                              void* d_out, int out_size)
{
    (void)in_sizes; (void)n_in;
    const float* x  = (const float*)d_in[0];
    const float* h0 = (const float*)d_in[1];
    const float* Wi = (const float*)d_in[2];
    const float* bi = (const float*)d_in[3];
    const float* Wh = (const float*)d_in[4];
    const float* bh = (const float*)d_in[5];
    float* out = (float*)d_out;

    cudaFuncSetAttribute(k_persist, cudaFuncAttributeMaxDynamicSharedMemorySize, SMEM_SZ);

    int has_hn = (out_size >= Bv * Tv * Hv + Bv * 2 * Hv) ? 1 : 0;

    k_init<<<512, 256>>>(h0, bi, bh);
    k_cvtx<<<32768, 256>>>(x);
    k_cvtw<<<dim3(32, 32, 4), dim3(32, 8)>>>(Wi, Wh);
    k_persist<<<GRID, NTHR, SMEM_SZ>>>(out, has_hn);
}

// round 14
// speedup vs baseline: 1.1776x; 1.1776x over previous
#include <cuda_runtime.h>
#include <cuda_fp16.h>
#include <math.h>
#include <stdint.h>

#define Bv 128
#define Tv 256
#define Hv 1024
#define GRID 256
#define NTHR 256

// ---------------- scratch -----------------------------------------------------
__device__ __half g_x16[(size_t)Bv * Tv * Hv];
__device__ __half g_Wt[4][(size_t)Hv * Hv];           // [n][k] fp16: 0:Wh0 1:Wi1 2:Wh1 3:Wi0
__device__ __half g_h0[2][Bv * Hv], g_h1[2][Bv * Hv]; // fp16 ping-pong states
__device__ float g_bsum[2 * Hv];
__device__ unsigned g_arrive, g_gen;

// ---------------- smem layout (dynamic, 96 KB -> 2 CTAs/SM) ----------------------
// [0, 64K)       resident W: 2 matrices x 16 chunk-tiles x 2KB (n16 x k64, SW128)
// [64K, 96K)     double-buffered A stream: per buffer A0|A1 (8KB each)
// combine (12KB) overlays A buffer 0 after mainloop
#define OFF_W     0
#define OFF_A(b)  (65536 + (b) * 16384)
#define OFF_CMB   65536
#define SMEM_SZ   98304

// ---------------- PTX helpers ---------------------------------------------------
__device__ __forceinline__ uint32_t smem_u32(const void* p) {
    uint32_t a;
    asm("{ .reg .u64 t; cvta.to.shared.u64 t, %1; cvt.u32.u64 %0, t; }" : "=r"(a) : "l"(p));
    return a;
}
__device__ __forceinline__ uint32_t swz(uint32_t o) { return o ^ ((o >> 3) & 0x70); }
__device__ __forceinline__ void cp16(uint32_t s, const void* g) {
    asm volatile("cp.async.cg.shared.global [%0], [%1], 16;" :: "r"(s), "l"(g));
}
__device__ __forceinline__ void ldm4(uint32_t* r, uint32_t addr) {
    asm volatile("ldmatrix.sync.aligned.m8n8.x4.shared.b16 {%0,%1,%2,%3}, [%4];"
        : "=r"(r[0]), "=r"(r[1]), "=r"(r[2]), "=r"(r[3]) : "r"(addr));
}
__device__ __forceinline__ void mma16816(float* c, const uint32_t* a, const uint32_t* b) {
    asm volatile("mma.sync.aligned.m16n8k16.row.col.f32.f16.f16.f32 "
        "{%0,%1,%2,%3}, {%4,%5,%6,%7}, {%8,%9}, {%0,%1,%2,%3};"
        : "+f"(c[0]), "+f"(c[1]), "+f"(c[2]), "+f"(c[3])
        : "r"(a[0]), "r"(a[1]), "r"(a[2]), "r"(a[3]), "r"(b[0]), "r"(b[1]));
}

// ---------------- grid barrier (busy-wait) ----------------------------------------
__device__ __forceinline__ void gbar(unsigned expect) {
    __threadfence();
    __syncthreads();
    if (threadIdx.x == 0) {
        unsigned a = atomicAdd(&g_arrive, 1u);
        if (a == GRID - 1) {
            atomicExch(&g_arrive, 0u);
            __threadfence();
            atomicAdd(&g_gen, 1u);
        } else {
            while (*(volatile unsigned*)&g_gen < expect) {}
        }
        __threadfence();
    }
    __syncthreads();
}

// ---------------- prep kernels -------------------------------------------------------
__global__ void __launch_bounds__(256) k_init(const float* __restrict__ h0in,
                                              const float* __restrict__ bi,
                                              const float* __restrict__ bh)
{
    int idx = blockIdx.x * 256 + threadIdx.x;   // 512 blocks = Bv*Hv
    if (idx == 0) { g_arrive = 0u; g_gen = 0u; }
    if (idx < 2 * Hv) g_bsum[idx] = bi[idx] + bh[idx];
    int j = idx & (Hv - 1);
    __half v0 = __float2half_rn(h0in[j]);
    __half v1 = __float2half_rn(h0in[Hv + j]);
    g_h0[0][idx] = v0; g_h0[1][idx] = v0;
    g_h1[0][idx] = v1; g_h1[1][idx] = v1;
}

__global__ void __launch_bounds__(256) k_cvtx(const float* __restrict__ x)
{
    size_t i = (size_t)blockIdx.x * 256 + threadIdx.x;
    float4 v = ((const float4*)x)[i];
    __half2 a = __floats2half2_rn(v.x, v.y);
    __half2 b = __floats2half2_rn(v.z, v.w);
    uint2 o;
    o.x = *(uint32_t*)&a;
    o.y = *(uint32_t*)&b;
    ((uint2*)g_x16)[i] = o;
}

__global__ void k_cvtw(const float* __restrict__ Wi, const float* __restrict__ Wh)
{
    __shared__ float t[32][33];
    int m = blockIdx.z;
    const float* W = (m == 0) ? Wh
                   : (m == 1) ? (Wi + (size_t)Hv * Hv)
                   : (m == 2) ? (Wh + (size_t)Hv * Hv) : Wi;
    int k0 = blockIdx.y * 32, n0 = blockIdx.x * 32;
    for (int r = threadIdx.y; r < 32; r += 8)
        t[r][threadIdx.x] = W[(size_t)(k0 + r) * Hv + n0 + threadIdx.x];
    __syncthreads();
    for (int r = threadIdx.y; r < 32; r += 8)
        g_Wt[m][(size_t)(n0 + r) * Hv + k0 + threadIdx.x] = __float2half_rn(t[threadIdx.x][r]);
}

// ---------------- persistent wavefront kernel -----------------------------------------
// 256 CTAs: blockIdx = ctn*4 + rh*2 + L. Patch = 64 rows x 16 cols, FULL pre-activation:
//   L0: h0[p] @ Wh0 + x_w @ Wi0        -> tanh -> h0[p^1]            (active w < Tv)
//   L1: h0[p] @ Wi1 + h1[p] @ Wh1      -> tanh -> h1[p^1], out[w-1]  (active w >= 1)
// 8 warps: wr (m32 half) x mat x kh. In-CTA 4-way combine, in-register epilogue.
// ONE grid barrier per wave; no cross-CTA partials.
__global__ void __launch_bounds__(NTHR, 2)
k_persist(float* __restrict__ out, int has_hn)
{
    extern __shared__ char smem[];
    const uint32_t sb = smem_u32(smem);
    const int tid  = threadIdx.x;
    const int lane = tid & 31;
    const int wid  = tid >> 5;
    const int L    = blockIdx.x & 1;
    const int rh   = (blockIdx.x >> 1) & 1;
    const int ctn  = blockIdx.x >> 2;          // 0..63
    const int r0   = rh * 64;
    const int nloc = ctn * 16;

    const int mat = wid & 1, kh = (wid >> 1) & 1, wr = wid >> 2;
    const int pidx = mat * 2 + kh;             // 0..3 combine group

    // A fragment addressing (two m16 tiles at rows wr*32, wr*32+16)
    const int mA    = wr * 32 + ((lane >> 3) & 1) * 8 + (lane & 7);
    const uint32_t xorA   = (uint32_t)((mA & 7) * 16);
    const uint32_t abase0 = (uint32_t)(mA * 128);
    const uint32_t abase1 = (uint32_t)((mA + 16) * 128);

    // W fragment addressing (n16 tile)
    const int nW    = ((lane >> 4) & 1) * 8 + (lane & 7);
    const uint32_t xorW  = (uint32_t)((nW & 7) * 16);
    const uint32_t wbase = (uint32_t)(nW * 128);

    // weight matrices for this CTA
    const __half* W0 = L ? g_Wt[1] : g_Wt[0];
    const __half* W1 = L ? g_Wt[2] : g_Wt[3];

    // ---- resident W: 2 matrices x [n16 x k1024], 16 chunk-tiles of 2KB each ----
    {
        const __half* Wm[2] = { W0, W1 };
#pragma unroll
        for (int r = 0; r < 16; r++) {
            int idx = tid + r * 256;           // 0..4095
            int m = idx >> 11;
            int w2 = idx & 2047;
            int c = w2 >> 7, w3 = w2 & 127;
            int row = w3 >> 3, kg = w3 & 7;
            cp16(sb + OFF_W + m * 32768 + c * 2048 + swz(row * 128 + kg * 16),
                 Wm[m] + (size_t)(nloc + row) * Hv + c * 64 + kg * 8);
        }
        asm volatile("cp.async.commit_group;" ::: "memory");
        asm volatile("cp.async.wait_group 0;" ::: "memory");
        __syncthreads();
    }

    unsigned expect = 0;

    for (int w = 0; w <= Tv; w++) {
        const int p = w & 1;
        const bool active = L ? (w >= 1) : (w < Tv);

        if (active) {
            const __half* A0 = g_h0[p] + (size_t)r0 * Hv;
            const __half* A1;
            size_t astr1;
            if (L) { A1 = g_h1[p] + (size_t)r0 * Hv;                 astr1 = Hv; }
            else   { A1 = g_x16 + ((size_t)r0 * Tv + w) * Hv;        astr1 = (size_t)Tv * Hv; }

            auto load_chunk = [&](int b, int c) {
#pragma unroll
                for (int r = 0; r < 2; r++) {
                    int i = tid + r * 256;
                    int row = i >> 3, kg = i & 7;
                    uint32_t so = swz(row * 128 + kg * 16);
                    cp16(sb + OFF_A(b) + so,        A0 + (size_t)row * Hv   + c * 64 + kg * 8);
                    cp16(sb + OFF_A(b) + 8192 + so, A1 + (size_t)row * astr1 + c * 64 + kg * 8);
                }
                asm volatile("cp.async.commit_group;" ::: "memory");
            };

            float acc[4][4];   // [mtile*2+ntile][regs]
#pragma unroll
            for (int i = 0; i < 4; i++)
#pragma unroll
                for (int q = 0; q < 4; q++) acc[i][q] = 0.f;

            load_chunk(0, 0);
            load_chunk(1, 1);

#pragma unroll 1
            for (int c = 0; c < 16; c++) {
                const int b = c & 1;
                if (c < 15) asm volatile("cp.async.wait_group 1;" ::: "memory");
                else        asm volatile("cp.async.wait_group 0;" ::: "memory");
                __syncthreads();

                const uint32_t sW = sb + OFF_W + mat * 32768 + c * 2048;
                const uint32_t sA = sb + OFF_A(b) + mat * 8192;
                uint32_t a0[4], a1[4], wf[4];
#pragma unroll
                for (int kq = 0; kq < 2; kq++) {
                    const int kk = kh * 2 + kq;
                    uint32_t ka = ((uint32_t)(kk * 32 + ((lane >> 4) & 1) * 16)) ^ xorA;
                    uint32_t kw = ((uint32_t)(kk * 32 + ((lane >> 3) & 1) * 16)) ^ xorW;
                    ldm4(a0, sA + abase0 + ka);
                    ldm4(a1, sA + abase1 + ka);
                    ldm4(wf, sW + wbase + kw);
                    mma16816(acc[0], a0, &wf[0]);
                    mma16816(acc[1], a0, &wf[2]);
                    mma16816(acc[2], a1, &wf[0]);
                    mma16816(acc[3], a1, &wf[2]);
                }
                __syncthreads();
                if (c + 2 < 16) load_chunk(b, c + 2);
            }

            // ---- 4-way combine over (mat, kh) via smem; pidx0 warps finish ----
            float* cmb = (float*)(smem + OFF_CMB);
            if (pidx) {
                float* dst = cmb + (size_t)(wr * 3 + pidx - 1) * 512;
#pragma unroll
                for (int f = 0; f < 16; f++)
                    dst[f * 32 + lane] = acc[f >> 2][f & 3];
            }
            __syncthreads();
            if (!pidx) {
#pragma unroll
                for (int f = 0; f < 16; f++) {
                    float s = acc[f >> 2][f & 3];
#pragma unroll
                    for (int u = 0; u < 3; u++)
                        s += cmb[(size_t)(wr * 3 + u) * 512 + f * 32 + lane];
                    acc[f >> 2][f & 3] = s;
                }
                // ---- in-register epilogue: bias + tanh, write state (+out) ----
                const int g = lane >> 2, tq = lane & 3;
                __half* Hs = L ? g_h1[p ^ 1] : g_h0[p ^ 1];
                const float* bsp = g_bsum + (L ? Hv : 0) + nloc;
#pragma unroll
                for (int i = 0; i < 2; i++) {
#pragma unroll
                    for (int j = 0; j < 2; j++) {
                        const float* a_ = acc[i * 2 + j];
                        int col = nloc + j * 8 + tq * 2;
                        float2 bs = *(const float2*)(bsp + j * 8 + tq * 2);
                        int rowa = r0 + wr * 32 + i * 16 + g;
                        int rowb = rowa + 8;
                        float z0 = tanhf(a_[0] + bs.x);
                        float z1 = tanhf(a_[1] + bs.y);
                        float z2 = tanhf(a_[2] + bs.x);
                        float z3 = tanhf(a_[3] + bs.y);
                        __half2 ha = __floats2half2_rn(z0, z1);
                        __half2 hb = __floats2half2_rn(z2, z3);
                        *(uint32_t*)&Hs[(size_t)rowa * Hv + col] = *(uint32_t*)&ha;
                        *(uint32_t*)&Hs[(size_t)rowb * Hv + col] = *(uint32_t*)&hb;
                        if (L) {
                            float2 oa; oa.x = z0; oa.y = z1;
                            float2 ob; ob.x = z2; ob.y = z3;
                            *(float2*)&out[((size_t)rowa * Tv + (w - 1)) * Hv + col] = oa;
                            *(float2*)&out[((size_t)rowb * Tv + (w - 1)) * Hv + col] = ob;
                            if (w == Tv && has_hn) {
                                *(float2*)&out[(size_t)Bv * Tv * Hv + (size_t)rowa * 2 * Hv + Hv + col] = oa;
                                *(float2*)&out[(size_t)Bv * Tv * Hv + (size_t)rowb * 2 * Hv + Hv + col] = ob;
                            }
                        } else if (w == Tv - 1 && has_hn) {
                            float2 oa; oa.x = z0; oa.y = z1;
                            float2 ob; ob.x = z2; ob.y = z3;
                            *(float2*)&out[(size_t)Bv * Tv * Hv + (size_t)rowa * 2 * Hv + col] = oa;
                            *(float2*)&out[(size_t)Bv * Tv * Hv + (size_t)rowb * 2 * Hv + col] = ob;
                        }
                    }
                }
            }
        }
        gbar(++expect);
    }
}

// ---------------- launcher -----------------------------------------------------------
extern "C" void kernel_launch(void* const* d_in, const int* in_sizes, int n_in,
                              void* d_out, int out_size)
{
    (void)in_sizes; (void)n_in;
    const float* x  = (const float*)d_in[0];
    const float* h0 = (const float*)d_in[1];
    const float* Wi = (const float*)d_in[2];
    const float* bi = (const float*)d_in[3];
    const float* Wh = (const float*)d_in[4];
    const float* bh = (const float*)d_in[5];
    float* out = (float*)d_out;

    cudaFuncSetAttribute(k_persist, cudaFuncAttributeMaxDynamicSharedMemorySize, SMEM_SZ);

    int has_hn = (out_size >= Bv * Tv * Hv + Bv * 2 * Hv) ? 1 : 0;

    k_init<<<512, 256>>>(h0, bi, bh);
    k_cvtx<<<32768, 256>>>(x);
    k_cvtw<<<dim3(32, 32, 4), dim3(32, 8)>>>(Wi, Wh);
    k_persist<<<GRID, NTHR, SMEM_SZ>>>(out, has_hn);
}

// round 15
// speedup vs baseline: 1.3548x; 1.1504x over previous
#include <cuda_runtime.h>
#include <cuda_fp16.h>
#include <math.h>
#include <stdint.h>

#define Bv 128
#define Tv 256
#define Hv 1024
#define GRID 256
#define NTHR 256

// ---------------- scratch -----------------------------------------------------
__device__ __half g_x16[(size_t)Bv * Tv * Hv];
__device__ __half g_Wt[4][(size_t)Hv * Hv];           // [n][k] fp16: 0:Wh0 1:Wi1 2:Wh1 3:Wi0
__device__ __half g_h0[2][Bv * Hv], g_h1[2][Bv * Hv]; // fp16 ping-pong states
__device__ float g_bsum[2 * Hv];
__device__ unsigned g_arrive, g_gen;

// ---------------- smem layout (dynamic, 112 KB -> 2 CTAs/SM) ----------------------
// [0, 64K)     resident W: 2 mats x 16 chunk-tiles x 2KB (n16 x k64, SW128)
// [64K, 112K)  per-warp A rings: 8 warps x 3 bufs x 2KB (16 rows x 128B, SW128)
// combine: mat0 warp m reads mat1 warp (2m+1)'s ring (dead at that point)
#define OFF_W     0
#define OFF_RING  65536
#define RING(w,b) (OFF_RING + (w) * 6144 + (b) * 2048)
#define SMEM_SZ   114688

// ---------------- PTX helpers ---------------------------------------------------
__device__ __forceinline__ uint32_t smem_u32(const void* p) {
    uint32_t a;
    asm("{ .reg .u64 t; cvta.to.shared.u64 t, %1; cvt.u32.u64 %0, t; }" : "=r"(a) : "l"(p));
    return a;
}
__device__ __forceinline__ uint32_t swz(uint32_t o) { return o ^ ((o >> 3) & 0x70); }
__device__ __forceinline__ void cp16(uint32_t s, const void* g) {
    asm volatile("cp.async.cg.shared.global [%0], [%1], 16;" :: "r"(s), "l"(g));
}
__device__ __forceinline__ void ldm4(uint32_t* r, uint32_t addr) {
    asm volatile("ldmatrix.sync.aligned.m8n8.x4.shared.b16 {%0,%1,%2,%3}, [%4];"
        : "=r"(r[0]), "=r"(r[1]), "=r"(r[2]), "=r"(r[3]) : "r"(addr));
}
__device__ __forceinline__ void mma16816(float* c, const uint32_t* a, const uint32_t* b) {
    asm volatile("mma.sync.aligned.m16n8k16.row.col.f32.f16.f16.f32 "
        "{%0,%1,%2,%3}, {%4,%5,%6,%7}, {%8,%9}, {%0,%1,%2,%3};"
        : "+f"(c[0]), "+f"(c[1]), "+f"(c[2]), "+f"(c[3])
        : "r"(a[0]), "r"(a[1]), "r"(a[2]), "r"(a[3]), "r"(b[0]), "r"(b[1]));
}

// ---------------- grid barrier (busy-wait) ----------------------------------------
__device__ __forceinline__ void gbar(unsigned expect) {
    __threadfence();
    __syncthreads();
    if (threadIdx.x == 0) {
        unsigned a = atomicAdd(&g_arrive, 1u);
        if (a == GRID - 1) {
            atomicExch(&g_arrive, 0u);
            __threadfence();
            atomicAdd(&g_gen, 1u);
        } else {
            while (*(volatile unsigned*)&g_gen < expect) {}
        }
        __threadfence();
    }
    __syncthreads();
}

// ---------------- prep kernels -------------------------------------------------------
__global__ void __launch_bounds__(256) k_init(const float* __restrict__ h0in,
                                              const float* __restrict__ bi,
                                              const float* __restrict__ bh)
{
    int idx = blockIdx.x * 256 + threadIdx.x;   // 512 blocks = Bv*Hv
    if (idx == 0) { g_arrive = 0u; g_gen = 0u; }
    if (idx < 2 * Hv) g_bsum[idx] = bi[idx] + bh[idx];
    int j = idx & (Hv - 1);
    __half v0 = __float2half_rn(h0in[j]);
    __half v1 = __float2half_rn(h0in[Hv + j]);
    g_h0[0][idx] = v0; g_h0[1][idx] = v0;
    g_h1[0][idx] = v1; g_h1[1][idx] = v1;
}

__global__ void __launch_bounds__(256) k_cvtx(const float* __restrict__ x)
{
    size_t i = (size_t)blockIdx.x * 256 + threadIdx.x;
    float4 v = ((const float4*)x)[i];
    __half2 a = __floats2half2_rn(v.x, v.y);
    __half2 b = __floats2half2_rn(v.z, v.w);
    uint2 o;
    o.x = *(uint32_t*)&a;
    o.y = *(uint32_t*)&b;
    ((uint2*)g_x16)[i] = o;
}

__global__ void k_cvtw(const float* __restrict__ Wi, const float* __restrict__ Wh)
{
    __shared__ float t[32][33];
    int m = blockIdx.z;
    const float* W = (m == 0) ? Wh
                   : (m == 1) ? (Wi + (size_t)Hv * Hv)
                   : (m == 2) ? (Wh + (size_t)Hv * Hv) : Wi;
    int k0 = blockIdx.y * 32, n0 = blockIdx.x * 32;
    for (int r = threadIdx.y; r < 32; r += 8)
        t[r][threadIdx.x] = W[(size_t)(k0 + r) * Hv + n0 + threadIdx.x];
    __syncthreads();
    for (int r = threadIdx.y; r < 32; r += 8)
        g_Wt[m][(size_t)(n0 + r) * Hv + k0 + threadIdx.x] = __float2half_rn(t[threadIdx.x][r]);
}

// ---------------- persistent wavefront kernel -----------------------------------------
// 256 CTAs: blockIdx = ctn*4 + rh*2 + L. Patch = 64 rows x 16 cols, FULL pre-activation:
//   L0: h0[p] @ Wh0 + x_w @ Wi0        -> tanh -> h0[p^1]            (active w < Tv)
//   L1: h0[p] @ Wi1 + h1[p] @ Wh1      -> tanh -> h1[p^1], out[w-1]  (active w >= 1)
// 8 warps = 4 m16-slices x 2 matrices. Warp-PRIVATE A streaming (3-deep cp.async ring,
// no __syncthreads in k-loop). W block-resident. One combine sync + ONE grid barrier.
__global__ void __launch_bounds__(NTHR, 2)
k_persist(float* __restrict__ out, int has_hn)
{
    extern __shared__ char smem[];
    const uint32_t sb = smem_u32(smem);
    const int tid  = threadIdx.x;
    const int lane = tid & 31;
    const int wid  = tid >> 5;
    const int L    = blockIdx.x & 1;
    const int rh   = (blockIdx.x >> 1) & 1;
    const int ctn  = blockIdx.x >> 2;          // 0..63
    const int r0   = rh * 64;
    const int nloc = ctn * 16;

    const int mat = wid & 1, ms = wid >> 1;    // matrix 0/1, m-slice 0..3
    const int rowbase = r0 + ms * 16;          // global row of this warp's m16

    // A fragment addressing within warp-private 16-row buffer
    const int mA    = ((lane >> 3) & 1) * 8 + (lane & 7);     // 0..15
    const uint32_t xorA  = (uint32_t)((mA & 7) * 16);
    const uint32_t abase = (uint32_t)(mA * 128);
    const uint32_t kaoff = (uint32_t)(((lane >> 4) & 1) * 16);

    // W fragment addressing (n16 tile)
    const int nW    = ((lane >> 4) & 1) * 8 + (lane & 7);
    const uint32_t xorW  = (uint32_t)((nW & 7) * 16);
    const uint32_t wbase = (uint32_t)(nW * 128);
    const uint32_t kwoff = (uint32_t)(((lane >> 3) & 1) * 16);

    // per-thread A-loader indices (4 cp16: rows 0..15, kg 0..7)
    const int ldrow = (lane >> 3);             // +4i below
    const int ldkg  = lane & 7;

    // ---- resident W: 2 mats x [n16 x k1024] (once) ----
    {
        const __half* Wm[2] = { L ? g_Wt[1] : g_Wt[0], L ? g_Wt[2] : g_Wt[3] };
#pragma unroll
        for (int r = 0; r < 16; r++) {
            int idx = tid + r * 256;           // 0..4095
            int m = idx >> 11;
            int w2 = idx & 2047;
            int c = w2 >> 7, w3 = w2 & 127;
            int row = w3 >> 3, kg = w3 & 7;
            cp16(sb + OFF_W + m * 32768 + c * 2048 + swz(row * 128 + kg * 16),
                 Wm[m] + (size_t)(nloc + row) * Hv + c * 64 + kg * 8);
        }
        asm volatile("cp.async.commit_group;" ::: "memory");
        asm volatile("cp.async.wait_group 0;" ::: "memory");
        __syncthreads();
    }

    const uint32_t sW = sb + OFF_W + mat * 32768;
    unsigned expect = 0;

    for (int w = 0; w <= Tv; w++) {
        const int p = w & 1;
        const bool active = L ? (w >= 1) : (w < Tv);

        if (active) {
            // this warp's A source (mat0: h0; mat1: h1 or x)
            const __half* Asrc;
            size_t astr;
            if (mat == 0) { Asrc = g_h0[p]; astr = Hv; }
            else if (L)   { Asrc = g_h1[p]; astr = Hv; }
            else          { Asrc = g_x16 + (size_t)w * Hv; astr = (size_t)Tv * Hv; }
            Asrc += (size_t)rowbase * astr;

            auto load_chunk = [&](int c) {
                uint32_t dst = sb + RING(wid, c % 3);
#pragma unroll
                for (int i = 0; i < 4; i++) {
                    int row = ldrow + i * 4;
                    cp16(dst + swz(row * 128 + ldkg * 16),
                         Asrc + (size_t)row * astr + c * 64 + ldkg * 8);
                }
                asm volatile("cp.async.commit_group;" ::: "memory");
            };

            float acc[2][4];
#pragma unroll
            for (int j = 0; j < 2; j++)
#pragma unroll
                for (int q = 0; q < 4; q++) acc[j][q] = 0.f;

            load_chunk(0);
            load_chunk(1);
            load_chunk(2);

#pragma unroll 1
            for (int c = 0; c < 16; c++) {
                if (c < 14)      asm volatile("cp.async.wait_group 2;" ::: "memory");
                else if (c == 14) asm volatile("cp.async.wait_group 1;" ::: "memory");
                else             asm volatile("cp.async.wait_group 0;" ::: "memory");
                __syncwarp();

                const uint32_t sA = sb + RING(wid, c % 3);
                const uint32_t sWc = sW + c * 2048;
                uint32_t a[4], wf[4];
#pragma unroll
                for (int kk = 0; kk < 4; kk++) {
                    uint32_t ka = ((uint32_t)(kk * 32) + kaoff) ^ xorA;
                    uint32_t kw = ((uint32_t)(kk * 32) + kwoff) ^ xorW;
                    ldm4(a, sA + abase + ka);
                    ldm4(wf, sWc + wbase + kw);
                    mma16816(acc[0], a, &wf[0]);
                    mma16816(acc[1], a, &wf[2]);
                }
                __syncwarp();
                if (c + 3 < 16) load_chunk(c + 3);
            }

            // ---- combine mats: mat1 warp writes its (dead) ring; mat0 fuses ----
            float* cmb = (float*)(smem + RING(ms * 2 + 1, 0));
            if (mat) {
#pragma unroll
                for (int f = 0; f < 8; f++)
                    cmb[f * 32 + lane] = acc[f >> 2][f & 3];
            }
            __syncthreads();
            if (!mat) {
                const int g = lane >> 2, tq = lane & 3;
                __half* Hs = L ? g_h1[p ^ 1] : g_h0[p ^ 1];
#pragma unroll
                for (int j = 0; j < 2; j++) {
                    int col = nloc + j * 8 + tq * 2;
                    float2 bs = *(const float2*)(g_bsum + (L ? Hv : 0) + col);
                    int rowa = rowbase + g, rowb = rowa + 8;
                    float z0 = tanhf(acc[j][0] + cmb[(j * 4 + 0) * 32 + lane] + bs.x);
                    float z1 = tanhf(acc[j][1] + cmb[(j * 4 + 1) * 32 + lane] + bs.y);
                    float z2 = tanhf(acc[j][2] + cmb[(j * 4 + 2) * 32 + lane] + bs.x);
                    float z3 = tanhf(acc[j][3] + cmb[(j * 4 + 3) * 32 + lane] + bs.y);
                    __half2 ha = __floats2half2_rn(z0, z1);
                    __half2 hb = __floats2half2_rn(z2, z3);
                    *(uint32_t*)&Hs[(size_t)rowa * Hv + col] = *(uint32_t*)&ha;
                    *(uint32_t*)&Hs[(size_t)rowb * Hv + col] = *(uint32_t*)&hb;
                    if (L) {
                        float2 oa; oa.x = z0; oa.y = z1;
                        float2 ob; ob.x = z2; ob.y = z3;
                        *(float2*)&out[((size_t)rowa * Tv + (w - 1)) * Hv + col] = oa;
                        *(float2*)&out[((size_t)rowb * Tv + (w - 1)) * Hv + col] = ob;
                        if (w == Tv && has_hn) {
                            *(float2*)&out[(size_t)Bv * Tv * Hv + (size_t)rowa * 2 * Hv + Hv + col] = oa;
                            *(float2*)&out[(size_t)Bv * Tv * Hv + (size_t)rowb * 2 * Hv + Hv + col] = ob;
                        }
                    } else if (w == Tv - 1 && has_hn) {
                        float2 oa; oa.x = z0; oa.y = z1;
                        float2 ob; ob.x = z2; ob.y = z3;
                        *(float2*)&out[(size_t)Bv * Tv * Hv + (size_t)rowa * 2 * Hv + col] = oa;
                        *(float2*)&out[(size_t)Bv * Tv * Hv + (size_t)rowb * 2 * Hv + col] = ob;
                    }
                }
            }
        }
        gbar(++expect);
    }
}

// ---------------- launcher -----------------------------------------------------------
extern "C" void kernel_launch(void* const* d_in, const int* in_sizes, int n_in,
                              void* d_out, int out_size)
{
    (void)in_sizes; (void)n_in;
    const float* x  = (const float*)d_in[0];
    const float* h0 = (const float*)d_in[1];
    const float* Wi = (const float*)d_in[2];
    const float* bi = (const float*)d_in[3];
    const float* Wh = (const float*)d_in[4];
    const float* bh = (const float*)d_in[5];
    float* out = (float*)d_out;

    cudaFuncSetAttribute(k_persist, cudaFuncAttributeMaxDynamicSharedMemorySize, SMEM_SZ);

    int has_hn = (out_size >= Bv * Tv * Hv + Bv * 2 * Hv) ? 1 : 0;

    k_init<<<512, 256>>>(h0, bi, bh);
    k_cvtx<<<32768, 256>>>(x);
    k_cvtw<<<dim3(32, 32, 4), dim3(32, 8)>>>(Wi, Wh);
    k_persist<<<GRID, NTHR, SMEM_SZ>>>(out, has_hn);
}

// round 16
// speedup vs baseline: 1.5463x; 1.1414x over previous
#include <cuda_runtime.h>
#include <cuda_fp16.h>
#include <math.h>
#include <stdint.h>

#define Bv 128
#define Tv 256
#define Hv 1024
#define GRID 256
#define NTHR 256

// ---------------- scratch -----------------------------------------------------
__device__ __half g_x16[(size_t)Bv * Tv * Hv];
__device__ __half g_Wt[4][(size_t)Hv * Hv];           // [n][k] fp16: 0:Wh0 1:Wi1 2:Wh1 3:Wi0
__device__ __half g_h0[2][Bv * Hv], g_h1[2][Bv * Hv]; // fp16 ping-pong states
__device__ float g_bsum[2 * Hv];
__device__ unsigned g_arrive, g_gen;

// ---------------- smem layout (dynamic, 68 KB -> 2 CTAs/SM) ----------------------
// [0, 64K)     A rings: 2 mats x 4 bufs x 8KB (64 rows x 128B, SW128)
// [64K, 68K)   W staging bounce (2 mats x 2KB), init only
// combine area (32KB) overlays the rings after the mainloop
#define RBUF(m,b) (((m) * 4 + (b)) * 8192)
#define OFF_WST   65536
#define SMEM_SZ   69632

// ---------------- PTX helpers ---------------------------------------------------
__device__ __forceinline__ uint32_t smem_u32(const void* p) {
    uint32_t a;
    asm("{ .reg .u64 t; cvta.to.shared.u64 t, %1; cvt.u32.u64 %0, t; }" : "=r"(a) : "l"(p));
    return a;
}
__device__ __forceinline__ uint32_t swz(uint32_t o) { return o ^ ((o >> 3) & 0x70); }
__device__ __forceinline__ void cp16(uint32_t s, const void* g) {
    asm volatile("cp.async.cg.shared.global [%0], [%1], 16;" :: "r"(s), "l"(g));
}
__device__ __forceinline__ void ldm4(uint32_t* r, uint32_t addr) {
    asm volatile("ldmatrix.sync.aligned.m8n8.x4.shared.b16 {%0,%1,%2,%3}, [%4];"
        : "=r"(r[0]), "=r"(r[1]), "=r"(r[2]), "=r"(r[3]) : "r"(addr));
}
__device__ __forceinline__ void mma16816(float* c, const uint32_t* a, const uint32_t* b) {
    asm volatile("mma.sync.aligned.m16n8k16.row.col.f32.f16.f16.f32 "
        "{%0,%1,%2,%3}, {%4,%5,%6,%7}, {%8,%9}, {%0,%1,%2,%3};"
        : "+f"(c[0]), "+f"(c[1]), "+f"(c[2]), "+f"(c[3])
        : "r"(a[0]), "r"(a[1]), "r"(a[2]), "r"(a[3]), "r"(b[0]), "r"(b[1]));
}
#define BARM(id) asm volatile("bar.sync %0, 128;" :: "r"(id) : "memory")

// ---------------- grid barrier (busy-wait) ----------------------------------------
__device__ __forceinline__ void gbar(unsigned expect) {
    __threadfence();
    __syncthreads();
    if (threadIdx.x == 0) {
        unsigned a = atomicAdd(&g_arrive, 1u);
        if (a == GRID - 1) {
            atomicExch(&g_arrive, 0u);
            __threadfence();
            atomicAdd(&g_gen, 1u);
        } else {
            while (*(volatile unsigned*)&g_gen < expect) {}
        }
        __threadfence();
    }
    __syncthreads();
}

// ---------------- prep kernels -------------------------------------------------------
__global__ void __launch_bounds__(256) k_init(const float* __restrict__ h0in,
                                              const float* __restrict__ bi,
                                              const float* __restrict__ bh)
{
    int idx = blockIdx.x * 256 + threadIdx.x;   // 512 blocks = Bv*Hv
    if (idx == 0) { g_arrive = 0u; g_gen = 0u; }
    if (idx < 2 * Hv) g_bsum[idx] = bi[idx] + bh[idx];
    int j = idx & (Hv - 1);
    __half v0 = __float2half_rn(h0in[j]);
    __half v1 = __float2half_rn(h0in[Hv + j]);
    g_h0[0][idx] = v0; g_h0[1][idx] = v0;
    g_h1[0][idx] = v1; g_h1[1][idx] = v1;
}

__global__ void __launch_bounds__(256) k_cvtx(const float* __restrict__ x)
{
    size_t i = (size_t)blockIdx.x * 256 + threadIdx.x;
    float4 v = ((const float4*)x)[i];
    __half2 a = __floats2half2_rn(v.x, v.y);
    __half2 b = __floats2half2_rn(v.z, v.w);
    uint2 o;
    o.x = *(uint32_t*)&a;
    o.y = *(uint32_t*)&b;
    ((uint2*)g_x16)[i] = o;
}

__global__ void k_cvtw(const float* __restrict__ Wi, const float* __restrict__ Wh)
{
    __shared__ float t[32][33];
    int m = blockIdx.z;
    const float* W = (m == 0) ? Wh
                   : (m == 1) ? (Wi + (size_t)Hv * Hv)
                   : (m == 2) ? (Wh + (size_t)Hv * Hv) : Wi;
    int k0 = blockIdx.y * 32, n0 = blockIdx.x * 32;
    for (int r = threadIdx.y; r < 32; r += 8)
        t[r][threadIdx.x] = W[(size_t)(k0 + r) * Hv + n0 + threadIdx.x];
    __syncthreads();
    for (int r = threadIdx.y; r < 32; r += 8)
        g_Wt[m][(size_t)(n0 + r) * Hv + k0 + threadIdx.x] = __float2half_rn(t[threadIdx.x][r]);
}

// ---------------- persistent wavefront kernel -----------------------------------------
// 256 CTAs: blockIdx = ctn*4 + rh*2 + L. Patch = 64 rows x 16 cols, FULL pre-activation:
//   L0: h0[p] @ Wh0 + x_w @ Wi0        -> tanh -> h0[p^1]            (active w < Tv)
//   L1: h0[p] @ Wi1 + h1[p] @ Wh1      -> tanh -> h1[p^1], out[w-1]  (active w >= 1)
// 8 warps = 2 mats x 4 kq (k16 stripe of each k64 chunk). W REGISTER-resident (64 regs).
// A: per-mat 4-deep cp.async ring, per-mat named barriers. Epilogue: 8-way combine.
__global__ void __launch_bounds__(NTHR, 2)
k_persist(float* __restrict__ out, int has_hn)
{
    extern __shared__ char smem[];
    const uint32_t sb = smem_u32(smem);
    const int tid  = threadIdx.x;
    const int lane = tid & 31;
    const int wid  = tid >> 5;
    const int L    = blockIdx.x & 1;
    const int rh   = (blockIdx.x >> 1) & 1;
    const int ctn  = blockIdx.x >> 2;          // 0..63
    const int r0   = rh * 64;
    const int nloc = ctn * 16;

    const int mat = wid >> 2, kq = wid & 3;

    // A fragment addressing: m16 slice frag, stripe kq within each chunk
    const int mA    = ((lane >> 3) & 1) * 8 + (lane & 7);     // 0..15
    const uint32_t xorA  = (uint32_t)((mA & 7) * 16);
    const uint32_t ka    = ((uint32_t)(kq * 32 + ((lane >> 4) & 1) * 16)) ^ xorA;
    const uint32_t abase = (uint32_t)(mA * 128);

    // W fragment addressing (n16 tile, stripe kq)
    const int nW    = ((lane >> 4) & 1) * 8 + (lane & 7);
    const uint32_t xorW = (uint32_t)((nW & 7) * 16);
    const uint32_t kw   = ((uint32_t)(kq * 32 + ((lane >> 3) & 1) * 16)) ^ xorW;
    const uint32_t wbase = (uint32_t)(nW * 128);

    // ---- preload W fragments into registers (16 chunks x 4 regs) ----
    uint32_t wreg[16][4];
    {
        const __half* WmA = L ? g_Wt[1] : g_Wt[0];
        const __half* WmB = L ? g_Wt[2] : g_Wt[3];
        const __half* Wsrc = (tid >> 7) ? WmB : WmA;
        int w3 = tid & 127, row = w3 >> 3, kg = w3 & 7;
        uint32_t dstb = sb + OFF_WST + (tid >> 7) * 2048 + swz(row * 128 + kg * 16);
#pragma unroll
        for (int c = 0; c < 16; c++) {
            cp16(dstb, Wsrc + (size_t)(nloc + row) * Hv + c * 64 + kg * 8);
            asm volatile("cp.async.commit_group;" ::: "memory");
            asm volatile("cp.async.wait_group 0;" ::: "memory");
            __syncthreads();
            ldm4(wreg[c], sb + OFF_WST + mat * 2048 + wbase + kw);
            __syncthreads();
        }
    }

    unsigned expect = 0;
    const int g = lane >> 2, tq = lane & 3;

    for (int w = 0; w <= Tv; w++) {
        const int p = w & 1;
        const bool active = L ? (w >= 1) : (w < Tv);

        if (active) {
            // this mat's A source (mat0: h0; mat1: h1 or x)
            const __half* Asrc;
            size_t astr;
            if (mat == 0) { Asrc = g_h0[p]; astr = Hv; }
            else if (L)   { Asrc = g_h1[p]; astr = Hv; }
            else          { Asrc = g_x16 + (size_t)w * Hv; astr = (size_t)Tv * Hv; }
            Asrc += (size_t)r0 * astr;

            // loader: this warp fills rows [kq*16, kq*16+16) of the 64-row chunk
            auto loadA = [&](int c) {
#pragma unroll
                for (int i = 0; i < 4; i++) {
                    int row = (kq << 4) + (lane >> 3) + i * 4;
                    cp16(sb + RBUF(mat, c & 3) + swz(row * 128 + (lane & 7) * 16),
                         Asrc + (size_t)row * astr + c * 64 + (lane & 7) * 8);
                }
                asm volatile("cp.async.commit_group;" ::: "memory");
            };

            float acc[4][2][4];
#pragma unroll
            for (int i = 0; i < 4; i++)
#pragma unroll
                for (int j = 0; j < 2; j++)
#pragma unroll
                    for (int q = 0; q < 4; q++) acc[i][j][q] = 0.f;

            loadA(0); loadA(1); loadA(2);

#pragma unroll
            for (int c = 0; c < 16; c++) {
                if (c < 14)       asm volatile("cp.async.wait_group 2;" ::: "memory");
                else if (c == 14) asm volatile("cp.async.wait_group 1;" ::: "memory");
                else              asm volatile("cp.async.wait_group 0;" ::: "memory");
                BARM(mat + 1);

                const uint32_t bufb = sb + RBUF(mat, c & 3) + ka;
#pragma unroll
                for (int i = 0; i < 4; i++) {
                    uint32_t a[4];
                    ldm4(a, bufb + (uint32_t)(i * 2048) + abase);
                    mma16816(acc[i][0], a, &wreg[c][0]);
                    mma16816(acc[i][1], a, &wreg[c][2]);
                }
                if (c + 3 < 16) loadA(c + 3);
            }

            // ---- 8-way combine (2 mats x 4 kq) via ring area ----
            __syncthreads();
            float* cmb = (float*)smem + wid * 1024;   // [64][16] fp32
#pragma unroll
            for (int i = 0; i < 4; i++)
#pragma unroll
                for (int j = 0; j < 2; j++) {
                    int ra = i * 16 + g, rb = ra + 8, c0 = j * 8 + tq * 2;
                    float2 v; v.x = acc[i][j][0]; v.y = acc[i][j][1];
                    float2 u; u.x = acc[i][j][2]; u.y = acc[i][j][3];
                    *(float2*)(cmb + ra * 16 + c0) = v;
                    *(float2*)(cmb + rb * 16 + c0) = u;
                }
            __syncthreads();

            // ---- warp-distributed epilogue: each warp owns 8 rows ----
            {
                int row = (wid << 3) + (lane >> 2);   // 0..63
                int c4  = (lane & 3) * 4;
                float4 s = make_float4(0.f, 0.f, 0.f, 0.f);
#pragma unroll
                for (int b = 0; b < 8; b++) {
                    float4 v = *(float4*)((float*)smem + b * 1024 + row * 16 + c4);
                    s.x += v.x; s.y += v.y; s.z += v.z; s.w += v.w;
                }
                float4 bs = *(const float4*)(g_bsum + (L ? Hv : 0) + nloc + c4);
                float z0 = tanhf(s.x + bs.x);
                float z1 = tanhf(s.y + bs.y);
                float z2 = tanhf(s.z + bs.z);
                float z3 = tanhf(s.w + bs.w);
                int grow = r0 + row;
                int gcol = nloc + c4;
                __half2 h01 = __floats2half2_rn(z0, z1);
                __half2 h23 = __floats2half2_rn(z2, z3);
                uint2 hp; hp.x = *(uint32_t*)&h01; hp.y = *(uint32_t*)&h23;
                __half* Hs = L ? g_h1[p ^ 1] : g_h0[p ^ 1];
                *(uint2*)&Hs[(size_t)grow * Hv + gcol] = hp;
                float4 z4; z4.x = z0; z4.y = z1; z4.z = z2; z4.w = z3;
                if (L) {
                    *(float4*)&out[((size_t)grow * Tv + (w - 1)) * Hv + gcol] = z4;
                    if (w == Tv && has_hn)
                        *(float4*)&out[(size_t)Bv * Tv * Hv + (size_t)grow * 2 * Hv + Hv + gcol] = z4;
                } else if (w == Tv - 1 && has_hn) {
                    *(float4*)&out[(size_t)Bv * Tv * Hv + (size_t)grow * 2 * Hv + gcol] = z4;
                }
            }
        }
        gbar(++expect);
    }
}

// ---------------- launcher -----------------------------------------------------------
extern "C" void kernel_launch(void* const* d_in, const int* in_sizes, int n_in,
                              void* d_out, int out_size)
{
    (void)in_sizes; (void)n_in;
    const float* x  = (const float*)d_in[0];
    const float* h0 = (const float*)d_in[1];
    const float* Wi = (const float*)d_in[2];
    const float* bi = (const float*)d_in[3];
    const float* Wh = (const float*)d_in[4];
    const float* bh = (const float*)d_in[5];
    float* out = (float*)d_out;

    cudaFuncSetAttribute(k_persist, cudaFuncAttributeMaxDynamicSharedMemorySize, SMEM_SZ);

    int has_hn = (out_size >= Bv * Tv * Hv + Bv * 2 * Hv) ? 1 : 0;

    k_init<<<512, 256>>>(h0, bi, bh);
    k_cvtx<<<32768, 256>>>(x);
    k_cvtw<<<dim3(32, 32, 4), dim3(32, 8)>>>(Wi, Wh);
    k_persist<<<GRID, NTHR, SMEM_SZ>>>(out, has_hn);
}

// round 17
// speedup vs baseline: 1.5491x; 1.0019x over previous
#include <cuda_runtime.h>
#include <cuda_fp16.h>
#include <math.h>
#include <stdint.h>

#define Bv 128
#define Tv 256
#define Hv 1024
#define GRID 256
#define NTHR 256

// ---------------- scratch -----------------------------------------------------
__device__ __half g_x16[(size_t)Bv * Tv * Hv];
__device__ __half g_Wt[4][(size_t)Hv * Hv];           // [n][k] fp16: 0:Wh0 1:Wi1 2:Wh1 3:Wi0
__device__ __half g_h0[4][Bv * Hv], g_h1[4][Bv * Hv]; // 4-slot state rings (h_t in slot t&3)
__device__ float g_bsum[2 * Hv];
__device__ unsigned g_arr[2];
__device__ int g_genW[2];

// ---------------- smem layout (dynamic, 68 KB -> 2 CTAs/SM) ----------------------
// [0, 64K)     A rings: 2 mats x 4 bufs x 8KB (64 rows x 128B, SW128)
// [64K, 68K)   W staging bounce (2 mats x 2KB), init only
// combine area (32KB) overlays the rings after the mainloop
#define RBUF(m,b) (((m) * 4 + (b)) * 8192)
#define OFF_WST   65536
#define SMEM_SZ   69632

// ---------------- PTX helpers ---------------------------------------------------
__device__ __forceinline__ uint32_t smem_u32(const void* p) {
    uint32_t a;
    asm("{ .reg .u64 t; cvta.to.shared.u64 t, %1; cvt.u32.u64 %0, t; }" : "=r"(a) : "l"(p));
    return a;
}
__device__ __forceinline__ uint32_t swz(uint32_t o) { return o ^ ((o >> 3) & 0x70); }
__device__ __forceinline__ void cp16(uint32_t s, const void* g) {
    asm volatile("cp.async.cg.shared.global [%0], [%1], 16;" :: "r"(s), "l"(g));
}
__device__ __forceinline__ void ldm4(uint32_t* r, uint32_t addr) {
    asm volatile("ldmatrix.sync.aligned.m8n8.x4.shared.b16 {%0,%1,%2,%3}, [%4];"
        : "=r"(r[0]), "=r"(r[1]), "=r"(r[2]), "=r"(r[3]) : "r"(addr));
}
__device__ __forceinline__ void mma16816(float* c, const uint32_t* a, const uint32_t* b) {
    asm volatile("mma.sync.aligned.m16n8k16.row.col.f32.f16.f16.f32 "
        "{%0,%1,%2,%3}, {%4,%5,%6,%7}, {%8,%9}, {%0,%1,%2,%3};"
        : "+f"(c[0]), "+f"(c[1]), "+f"(c[2]), "+f"(c[3])
        : "r"(a[0]), "r"(a[1]), "r"(a[2]), "r"(a[3]), "r"(b[0]), "r"(b[1]));
}
#define BARM(id) asm volatile("bar.sync %0, 128;" :: "r"(id) : "memory")

// ---------------- prep kernels -------------------------------------------------------
__global__ void __launch_bounds__(256) k_init(const float* __restrict__ h0in,
                                              const float* __restrict__ bi,
                                              const float* __restrict__ bh)
{
    int idx = blockIdx.x * 256 + threadIdx.x;   // 512 blocks = Bv*Hv
    if (idx == 0) { g_arr[0] = 0u; g_arr[1] = 0u; g_genW[0] = 0; g_genW[1] = 0; }
    if (idx < 2 * Hv) g_bsum[idx] = bi[idx] + bh[idx];
    int j = idx & (Hv - 1);
    // initial states h_{-1} live in slot 3
    g_h0[3][idx] = __float2half_rn(h0in[j]);
    g_h1[3][idx] = __float2half_rn(h0in[Hv + j]);
}

__global__ void __launch_bounds__(256) k_cvtx(const float* __restrict__ x)
{
    size_t i = (size_t)blockIdx.x * 256 + threadIdx.x;
    float4 v = ((const float4*)x)[i];
    __half2 a = __floats2half2_rn(v.x, v.y);
    __half2 b = __floats2half2_rn(v.z, v.w);
    uint2 o;
    o.x = *(uint32_t*)&a;
    o.y = *(uint32_t*)&b;
    ((uint2*)g_x16)[i] = o;
}

__global__ void k_cvtw(const float* __restrict__ Wi, const float* __restrict__ Wh)
{
    __shared__ float t[32][33];
    int m = blockIdx.z;
    const float* W = (m == 0) ? Wh
                   : (m == 1) ? (Wi + (size_t)Hv * Hv)
                   : (m == 2) ? (Wh + (size_t)Hv * Hv) : Wi;
    int k0 = blockIdx.y * 32, n0 = blockIdx.x * 32;
    for (int r = threadIdx.y; r < 32; r += 8)
        t[r][threadIdx.x] = W[(size_t)(k0 + r) * Hv + n0 + threadIdx.x];
    __syncthreads();
    for (int r = threadIdx.y; r < 32; r += 8)
        g_Wt[m][(size_t)(n0 + r) * Hv + k0 + threadIdx.x] = __float2half_rn(t[threadIdx.x][r]);
}

// ---------------- persistent wavefront kernel -----------------------------------------
// 256 CTAs: blockIdx = ctn*4 + rh*2 + L. Patch = 64 rows x 16 cols, FULL pre-activation.
//   L0(w): h0_{w-1} @ Wh0 + x_w @ Wi0 -> tanh -> h0_w              (active w < Tv)
//   L1(w): h0_{w-1} @ Wi1 + h1_{w-2} @ Wh1 -> tanh -> h1_{w-1}, out (active w >= 1)
// TWO phase-shifted group barriers (128 CTAs each):
//   L0 waits gen0 >= w && gen1 >= w-2 (WAR bound on 4-slot h0 ring)
//   L1 waits gen0 >= w && gen1 >= w
// -> L0 group runs up to 2 waves ahead; overheads overlap across groups.
__global__ void __launch_bounds__(NTHR, 2)
k_persist(float* __restrict__ out, int has_hn)
{
    extern __shared__ char smem[];
    const uint32_t sb = smem_u32(smem);
    const int tid  = threadIdx.x;
    const int lane = tid & 31;
    const int wid  = tid >> 5;
    const int L    = blockIdx.x & 1;
    const int rh   = (blockIdx.x >> 1) & 1;
    const int ctn  = blockIdx.x >> 2;          // 0..63
    const int r0   = rh * 64;
    const int nloc = ctn * 16;

    const int mat = wid >> 2, kq = wid & 3;

    // A fragment addressing: m16 slice frag, stripe kq within each chunk
    const int mA    = ((lane >> 3) & 1) * 8 + (lane & 7);     // 0..15
    const uint32_t xorA  = (uint32_t)((mA & 7) * 16);
    const uint32_t ka    = ((uint32_t)(kq * 32 + ((lane >> 4) & 1) * 16)) ^ xorA;
    const uint32_t abase = (uint32_t)(mA * 128);

    // W fragment addressing (n16 tile, stripe kq)
    const int nW    = ((lane >> 4) & 1) * 8 + (lane & 7);
    const uint32_t xorW = (uint32_t)((nW & 7) * 16);
    const uint32_t kw   = ((uint32_t)(kq * 32 + ((lane >> 3) & 1) * 16)) ^ xorW;
    const uint32_t wbase = (uint32_t)(nW * 128);

    // ---- preload W fragments into registers (16 chunks x 4 regs) ----
    uint32_t wreg[16][4];
    {
        const __half* WmA = L ? g_Wt[1] : g_Wt[0];
        const __half* WmB = L ? g_Wt[2] : g_Wt[3];
        const __half* Wsrc = (tid >> 7) ? WmB : WmA;
        int w3 = tid & 127, row = w3 >> 3, kg = w3 & 7;
        uint32_t dstb = sb + OFF_WST + (tid >> 7) * 2048 + swz(row * 128 + kg * 16);
#pragma unroll
        for (int c = 0; c < 16; c++) {
            cp16(dstb, Wsrc + (size_t)(nloc + row) * Hv + c * 64 + kg * 8);
            asm volatile("cp.async.commit_group;" ::: "memory");
            asm volatile("cp.async.wait_group 0;" ::: "memory");
            __syncthreads();
            ldm4(wreg[c], sb + OFF_WST + mat * 2048 + wbase + kw);
            __syncthreads();
        }
    }

    const int g = lane >> 2, tq = lane & 3;

    for (int w = 0; w <= Tv; w++) {
        // ---- phase-shifted wait ----
        if (tid == 0) {
            volatile int* gp = g_genW;
            if (L == 0) { while (gp[0] < w || gp[1] < w - 2) {} }
            else        { while (gp[0] < w || gp[1] < w) {} }
            __threadfence();
        }
        __syncthreads();

        const bool active = L ? (w >= 1) : (w < Tv);

        if (active) {
            const int s_h0r = (w - 1) & 3;
            // this mat's A source (mat0: h0; mat1: h1 or x)
            const __half* Asrc;
            size_t astr;
            if (mat == 0) { Asrc = g_h0[s_h0r]; astr = Hv; }
            else if (L)   { Asrc = g_h1[(w - 2) & 3]; astr = Hv; }
            else          { Asrc = g_x16 + (size_t)w * Hv; astr = (size_t)Tv * Hv; }
            Asrc += (size_t)r0 * astr;

            // loader: this warp fills rows [kq*16, kq*16+16) of the 64-row chunk
            auto loadA = [&](int c) {
#pragma unroll
                for (int i = 0; i < 4; i++) {
                    int row = (kq << 4) + (lane >> 3) + i * 4;
                    cp16(sb + RBUF(mat, c & 3) + swz(row * 128 + (lane & 7) * 16),
                         Asrc + (size_t)row * astr + c * 64 + (lane & 7) * 8);
                }
                asm volatile("cp.async.commit_group;" ::: "memory");
            };

            float acc[4][2][4];
#pragma unroll
            for (int i = 0; i < 4; i++)
#pragma unroll
                for (int j = 0; j < 2; j++)
#pragma unroll
                    for (int q = 0; q < 4; q++) acc[i][j][q] = 0.f;

            loadA(0); loadA(1); loadA(2);

#pragma unroll
            for (int c = 0; c < 16; c++) {
                if (c < 14)       asm volatile("cp.async.wait_group 2;" ::: "memory");
                else if (c == 14) asm volatile("cp.async.wait_group 1;" ::: "memory");
                else              asm volatile("cp.async.wait_group 0;" ::: "memory");
                BARM(mat + 1);

                const uint32_t bufb = sb + RBUF(mat, c & 3) + ka;
#pragma unroll
                for (int i = 0; i < 4; i++) {
                    uint32_t a[4];
                    ldm4(a, bufb + (uint32_t)(i * 2048) + abase);
                    mma16816(acc[i][0], a, &wreg[c][0]);
                    mma16816(acc[i][1], a, &wreg[c][2]);
                }
                if (c + 3 < 16) loadA(c + 3);
            }

            // ---- 8-way combine (2 mats x 4 kq) via ring area ----
            __syncthreads();
            float* cmb = (float*)smem + wid * 1024;   // [64][16] fp32
#pragma unroll
            for (int i = 0; i < 4; i++)
#pragma unroll
                for (int j = 0; j < 2; j++) {
                    int ra = i * 16 + g, rb = ra + 8, c0 = j * 8 + tq * 2;
                    float2 v; v.x = acc[i][j][0]; v.y = acc[i][j][1];
                    float2 u; u.x = acc[i][j][2]; u.y = acc[i][j][3];
                    *(float2*)(cmb + ra * 16 + c0) = v;
                    *(float2*)(cmb + rb * 16 + c0) = u;
                }
            __syncthreads();

            // ---- warp-distributed epilogue: each warp owns 8 rows ----
            {
                int row = (wid << 3) + (lane >> 2);   // 0..63
                int c4  = (lane & 3) * 4;
                float4 s = make_float4(0.f, 0.f, 0.f, 0.f);
#pragma unroll
                for (int b = 0; b < 8; b++) {
                    float4 v = *(float4*)((float*)smem + b * 1024 + row * 16 + c4);
                    s.x += v.x; s.y += v.y; s.z += v.z; s.w += v.w;
                }
                float4 bs = *(const float4*)(g_bsum + (L ? Hv : 0) + nloc + c4);
                float z0 = tanhf(s.x + bs.x);
                float z1 = tanhf(s.y + bs.y);
                float z2 = tanhf(s.z + bs.z);
                float z3 = tanhf(s.w + bs.w);
                int grow = r0 + row;
                int gcol = nloc + c4;
                __half2 h01 = __floats2half2_rn(z0, z1);
                __half2 h23 = __floats2half2_rn(z2, z3);
                uint2 hp; hp.x = *(uint32_t*)&h01; hp.y = *(uint32_t*)&h23;
                __half* Hs = L ? g_h1[(w - 1) & 3] : g_h0[w & 3];
                *(uint2*)&Hs[(size_t)grow * Hv + gcol] = hp;
                float4 z4; z4.x = z0; z4.y = z1; z4.z = z2; z4.w = z3;
                if (L) {
                    *(float4*)&out[((size_t)grow * Tv + (w - 1)) * Hv + gcol] = z4;
                    if (w == Tv && has_hn)
                        *(float4*)&out[(size_t)Bv * Tv * Hv + (size_t)grow * 2 * Hv + Hv + gcol] = z4;
                } else if (w == Tv - 1 && has_hn) {
                    *(float4*)&out[(size_t)Bv * Tv * Hv + (size_t)grow * 2 * Hv + gcol] = z4;
                }
            }
        }

        // ---- group arrive ----
        __syncthreads();
        if (tid == 0) {
            __threadfence();
            unsigned old = atomicAdd(&g_arr[L], 1u);
            if (old == 127u) {
                atomicExch(&g_arr[L], 0u);
                __threadfence();
                atomicAdd((unsigned*)&g_genW[L], 1u);
            }
        }
    }
}

// ---------------- launcher -----------------------------------------------------------
extern "C" void kernel_launch(void* const* d_in, const int* in_sizes, int n_in,
                              void* d_out, int out_size)
{
    (void)in_sizes; (void)n_in;
    const float* x  = (const float*)d_in[0];
    const float* h0 = (const float*)d_in[1];
    const float* Wi = (const float*)d_in[2];
    const float* bi = (const float*)d_in[3];
    const float* Wh = (const float*)d_in[4];
    const float* bh = (const float*)d_in[5];
    float* out = (float*)d_out;

    cudaFuncSetAttribute(k_persist, cudaFuncAttributeMaxDynamicSharedMemorySize, SMEM_SZ);

    int has_hn = (out_size >= Bv * Tv * Hv + Bv * 2 * Hv) ? 1 : 0;

    k_init<<<512, 256>>>(h0, bi, bh);
    k_cvtx<<<32768, 256>>>(x);
    k_cvtw<<<dim3(32, 32, 4), dim3(32, 8)>>>(Wi, Wh);
    k_persist<<<GRID, NTHR, SMEM_SZ>>>(out, has_hn);
}